// round 1
// baseline (speedup 1.0000x reference)
#include <cuda_runtime.h>
#include <math.h>

#define S_LEN 4096
#define BATCH 2
#define DM    768
#define DFF   3072
#define NH    12
#define DK    64
#define NTOK  (BATCH * S_LEN)

// ---------------- scratch (device globals: no allocation allowed) ----------
__device__ float g_h  [NTOK * DM];
__device__ float g_q  [NTOK * DM];
__device__ float g_k  [NTOK * DM];
__device__ float g_v  [NTOK * DM];
__device__ float g_ctx[NTOK * DM];
__device__ float g_x2 [NTOK * DM];
__device__ float g_ff [NTOK * DFF];

// ---------------- layernorm-ish (scalar alpha/beta, ddof=1 std) -----------
__global__ void norm_kernel(const float* __restrict__ x, float* __restrict__ out,
                            const float* __restrict__ alpha, const float* __restrict__ beta) {
    const int row = blockIdx.x;
    const float* xr = x + (size_t)row * DM;
    float* orow = out + (size_t)row * DM;

    // 768 cols, 256 threads -> 3 per thread
    float v0 = xr[threadIdx.x];
    float v1 = xr[threadIdx.x + 256];
    float v2 = xr[threadIdx.x + 512];
    float s  = v0 + v1 + v2;
    float sq = v0 * v0 + v1 * v1 + v2 * v2;

    __shared__ float red0[8], red1[8];
    __shared__ float s_mean, s_scale, s_beta;
    #pragma unroll
    for (int o = 16; o > 0; o >>= 1) {
        s  += __shfl_xor_sync(0xffffffffu, s,  o);
        sq += __shfl_xor_sync(0xffffffffu, sq, o);
    }
    const int warp = threadIdx.x >> 5, lane = threadIdx.x & 31;
    if (lane == 0) { red0[warp] = s; red1[warp] = sq; }
    __syncthreads();
    if (threadIdx.x == 0) {
        float S = 0.f, SQ = 0.f;
        #pragma unroll
        for (int i = 0; i < 8; i++) { S += red0[i]; SQ += red1[i]; }
        const float mean = S / (float)DM;
        float var = (SQ - (float)DM * mean * mean) / (float)(DM - 1);
        var = fmaxf(var, 0.f);
        s_mean  = mean;
        s_scale = alpha[0] / (sqrtf(var) + 1e-6f);
        s_beta  = beta[0];
    }
    __syncthreads();
    const float mean = s_mean, scale = s_scale, bb = s_beta;
    orow[threadIdx.x]       = (v0 - mean) * scale + bb;
    orow[threadIdx.x + 256] = (v1 - mean) * scale + bb;
    orow[threadIdx.x + 512] = (v2 - mean) * scale + bb;
}

// ---------------- SGEMM: C[M,N] = A[M,K] @ W[N,K]^T + bias (+res) (+relu) --
// M%128==0, N%128==0, K%16==0 guaranteed by problem sizes.
template <bool RELU, bool HAS_RES>
__global__ void __launch_bounds__(256, 2)
gemm_kernel(const float* __restrict__ A, const float* __restrict__ W,
            const float* __restrict__ bias, const float* __restrict__ res,
            float* __restrict__ C, int M, int N, int K) {
    __shared__ float As[16][132];
    __shared__ float Bs[16][132];

    const int bm = blockIdx.y * 128;
    const int bn = blockIdx.x * 128;
    const int t  = threadIdx.x;
    const int tx = t & 15, ty = t >> 4;

    const float* Ab = A + (size_t)bm * K;
    const float* Wb = W + (size_t)bn * K;

    float c[8][8];
    #pragma unroll
    for (int i = 0; i < 8; i++)
        #pragma unroll
        for (int j = 0; j < 8; j++) c[i][j] = 0.f;

    for (int k0 = 0; k0 < K; k0 += 16) {
        #pragma unroll
        for (int p = 0; p < 2; p++) {
            const int f   = t + p * 256;
            const int row = f >> 2;
            const int kg  = (f & 3) * 4;
            float4 av = *(const float4*)(Ab + (size_t)row * K + k0 + kg);
            As[kg + 0][row] = av.x; As[kg + 1][row] = av.y;
            As[kg + 2][row] = av.z; As[kg + 3][row] = av.w;
            float4 wv = *(const float4*)(Wb + (size_t)row * K + k0 + kg);
            Bs[kg + 0][row] = wv.x; Bs[kg + 1][row] = wv.y;
            Bs[kg + 2][row] = wv.z; Bs[kg + 3][row] = wv.w;
        }
        __syncthreads();
        #pragma unroll
        for (int kk = 0; kk < 16; kk++) {
            float a[8], b[8];
            #pragma unroll
            for (int i = 0; i < 8; i++) a[i] = As[kk][ty * 8 + i];
            #pragma unroll
            for (int j = 0; j < 8; j++) b[j] = Bs[kk][tx * 8 + j];
            #pragma unroll
            for (int i = 0; i < 8; i++)
                #pragma unroll
                for (int j = 0; j < 8; j++) c[i][j] = fmaf(a[i], b[j], c[i][j]);
        }
        __syncthreads();
    }

    #pragma unroll
    for (int i = 0; i < 8; i++) {
        const int m = bm + ty * 8 + i;
        #pragma unroll
        for (int j = 0; j < 8; j++) {
            const int n = bn + tx * 8 + j;
            float v = c[i][j] + bias[n];
            if (HAS_RES) v += res[(size_t)m * N + n];
            if (RELU)    v = fmaxf(v, 0.f);
            C[(size_t)m * N + n] = v;
        }
    }
}

// ---------------- flash attention, fp32, BM=BN=64, D=64 --------------------
// layouts: Q/K/V/O are [B, S, H*DK] row-major; head h lives at col h*64.
#define ATT_STRIDE 65
#define ATT_SMEM_FLOATS (3 * 64 * ATT_STRIDE)

__global__ void __launch_bounds__(256, 2)
attn_kernel(const float* __restrict__ Q, const float* __restrict__ K,
            const float* __restrict__ V, const int* __restrict__ mask,
            float* __restrict__ O) {
    extern __shared__ float smem[];
    float* Qs  = smem;                       // [64][65]
    float* KVs = smem + 64 * ATT_STRIDE;     // [64][65] (K, then reused for V)
    float* Ss  = smem + 2 * 64 * ATT_STRIDE; // [64][65]
    __shared__ float mrow[64], lrow[64], frow[64];
    __shared__ int   mk[64];

    const int q0 = blockIdx.x * 64;
    const int h  = blockIdx.y;
    const int b  = blockIdx.z;
    const int t  = threadIdx.x;
    const int tx = t & 15, ty = t >> 4;

    const size_t base = (size_t)b * S_LEN * DM + (size_t)h * DK;

    // load Q tile
    for (int f = t; f < 64 * 16; f += 256) {
        const int row = f >> 4;
        const int dg  = (f & 15) * 4;
        float4 v4 = *(const float4*)(Q + base + (size_t)(q0 + row) * DM + dg);
        float* dst = Qs + row * ATT_STRIDE + dg;
        dst[0] = v4.x; dst[1] = v4.y; dst[2] = v4.z; dst[3] = v4.w;
    }
    if (t < 64) { mrow[t] = -INFINITY; lrow[t] = 0.f; }

    float o[4][4];
    #pragma unroll
    for (int i = 0; i < 4; i++)
        #pragma unroll
        for (int j = 0; j < 4; j++) o[i][j] = 0.f;

    __syncthreads();

    for (int k0 = 0; k0 < S_LEN; k0 += 64) {
        // load K tile + mask
        for (int f = t; f < 64 * 16; f += 256) {
            const int row = f >> 4;
            const int dg  = (f & 15) * 4;
            float4 v4 = *(const float4*)(K + base + (size_t)(k0 + row) * DM + dg);
            float* dst = KVs + row * ATT_STRIDE + dg;
            dst[0] = v4.x; dst[1] = v4.y; dst[2] = v4.z; dst[3] = v4.w;
        }
        if (t < 64) mk[t] = mask[(size_t)b * S_LEN + k0 + t];
        __syncthreads();

        // scores s = Q K^T
        float s[4][4];
        #pragma unroll
        for (int i = 0; i < 4; i++)
            #pragma unroll
            for (int j = 0; j < 4; j++) s[i][j] = 0.f;
        #pragma unroll 8
        for (int d = 0; d < 64; d++) {
            float a[4], bb[4];
            #pragma unroll
            for (int i = 0; i < 4; i++) a[i]  = Qs[(ty * 4 + i) * ATT_STRIDE + d];
            #pragma unroll
            for (int j = 0; j < 4; j++) bb[j] = KVs[(tx * 4 + j) * ATT_STRIDE + d];
            #pragma unroll
            for (int i = 0; i < 4; i++)
                #pragma unroll
                for (int j = 0; j < 4; j++) s[i][j] = fmaf(a[i], bb[j], s[i][j]);
        }
        #pragma unroll
        for (int i = 0; i < 4; i++)
            #pragma unroll
            for (int j = 0; j < 4; j++) {
                const int kj = tx * 4 + j;
                const float v = mk[kj] ? s[i][j] * 0.125f : -1e9f;
                Ss[(ty * 4 + i) * ATT_STRIDE + kj] = v;
            }
        __syncthreads();

        // load V into KVs (K tile no longer needed) — no hazard with softmax
        for (int f = t; f < 64 * 16; f += 256) {
            const int row = f >> 4;
            const int dg  = (f & 15) * 4;
            float4 v4 = *(const float4*)(V + base + (size_t)(k0 + row) * DM + dg);
            float* dst = KVs + row * ATT_STRIDE + dg;
            dst[0] = v4.x; dst[1] = v4.y; dst[2] = v4.z; dst[3] = v4.w;
        }

        // online softmax update: 4 threads per query row
        {
            const int r = t >> 2, cc = t & 3;
            float mloc = -INFINITY;
            #pragma unroll
            for (int j = cc * 16; j < cc * 16 + 16; j++)
                mloc = fmaxf(mloc, Ss[r * ATT_STRIDE + j]);
            mloc = fmaxf(mloc, __shfl_xor_sync(0xffffffffu, mloc, 1));
            mloc = fmaxf(mloc, __shfl_xor_sync(0xffffffffu, mloc, 2));
            const float mold = mrow[r];
            const float mnew = fmaxf(mold, mloc);
            float lloc = 0.f;
            #pragma unroll
            for (int j = cc * 16; j < cc * 16 + 16; j++) {
                const float p = __expf(Ss[r * ATT_STRIDE + j] - mnew);
                Ss[r * ATT_STRIDE + j] = p;
                lloc += p;
            }
            lloc += __shfl_xor_sync(0xffffffffu, lloc, 1);
            lloc += __shfl_xor_sync(0xffffffffu, lloc, 2);
            if (cc == 0) {
                const float fac = __expf(mold - mnew);
                frow[r] = fac;
                lrow[r] = lrow[r] * fac + lloc;
                mrow[r] = mnew;
            }
        }
        __syncthreads();

        // rescale O, then O += P @ V
        #pragma unroll
        for (int i = 0; i < 4; i++) {
            const float fac = frow[ty * 4 + i];
            #pragma unroll
            for (int j = 0; j < 4; j++) o[i][j] *= fac;
        }
        #pragma unroll 8
        for (int k = 0; k < 64; k++) {
            float a[4], bb[4];
            #pragma unroll
            for (int i = 0; i < 4; i++) a[i]  = Ss[(ty * 4 + i) * ATT_STRIDE + k];
            #pragma unroll
            for (int j = 0; j < 4; j++) bb[j] = KVs[k * ATT_STRIDE + tx * 4 + j];
            #pragma unroll
            for (int i = 0; i < 4; i++)
                #pragma unroll
                for (int j = 0; j < 4; j++) o[i][j] = fmaf(a[i], bb[j], o[i][j]);
        }
        __syncthreads();
    }

    #pragma unroll
    for (int i = 0; i < 4; i++) {
        const float inv = 1.f / lrow[ty * 4 + i];
        #pragma unroll
        for (int j = 0; j < 4; j++)
            O[base + (size_t)(q0 + ty * 4 + i) * DM + tx * 4 + j] = o[i][j] * inv;
    }
}

// ---------------------------------------------------------------------------
extern "C" void kernel_launch(void* const* d_in, const int* in_sizes, int n_in,
                              void* d_out, int out_size) {
    const float* x      = (const float*)d_in[0];
    const int*   mask   = (const int*)  d_in[1];
    const float* wq     = (const float*)d_in[2];
    const float* bq     = (const float*)d_in[3];
    const float* wk     = (const float*)d_in[4];
    const float* bk     = (const float*)d_in[5];
    const float* wv     = (const float*)d_in[6];
    const float* bv     = (const float*)d_in[7];
    const float* wo     = (const float*)d_in[8];
    const float* bo     = (const float*)d_in[9];
    const float* w1     = (const float*)d_in[10];
    const float* b1     = (const float*)d_in[11];
    const float* w2     = (const float*)d_in[12];
    const float* b2     = (const float*)d_in[13];
    const float* alpha1 = (const float*)d_in[14];
    const float* beta1  = (const float*)d_in[15];
    const float* alpha2 = (const float*)d_in[16];
    const float* beta2  = (const float*)d_in[17];
    float* out = (float*)d_out;

    float *h, *q, *k, *v, *ctx, *x2, *ff;
    cudaGetSymbolAddress((void**)&h,   g_h);
    cudaGetSymbolAddress((void**)&q,   g_q);
    cudaGetSymbolAddress((void**)&k,   g_k);
    cudaGetSymbolAddress((void**)&v,   g_v);
    cudaGetSymbolAddress((void**)&ctx, g_ctx);
    cudaGetSymbolAddress((void**)&x2,  g_x2);
    cudaGetSymbolAddress((void**)&ff,  g_ff);

    cudaFuncSetAttribute(attn_kernel, cudaFuncAttributeMaxDynamicSharedMemorySize,
                         ATT_SMEM_FLOATS * (int)sizeof(float));

    const dim3 gemm_qkv(DM / 128, NTOK / 128);   // N=768
    const dim3 gemm_ff1(DFF / 128, NTOK / 128);  // N=3072
    const dim3 attn_grid(S_LEN / 64, NH, BATCH);

    // 1. h = norm1(x)
    norm_kernel<<<NTOK, 256>>>(x, h, alpha1, beta1);
    // 2-4. q,k,v projections
    gemm_kernel<false, false><<<gemm_qkv, 256>>>(h, wq, bq, nullptr, q, NTOK, DM, DM);
    gemm_kernel<false, false><<<gemm_qkv, 256>>>(h, wk, bk, nullptr, k, NTOK, DM, DM);
    gemm_kernel<false, false><<<gemm_qkv, 256>>>(h, wv, bv, nullptr, v, NTOK, DM, DM);
    // 5. attention -> ctx
    attn_kernel<<<attn_grid, 256, ATT_SMEM_FLOATS * sizeof(float)>>>(q, k, v, mask, ctx);
    // 6. x2 = x + ctx @ wo^T + bo
    gemm_kernel<false, true><<<gemm_qkv, 256>>>(ctx, wo, bo, x, x2, NTOK, DM, DM);
    // 7. h = norm2(x2)
    norm_kernel<<<NTOK, 256>>>(x2, h, alpha2, beta2);
    // 8. ff = relu(h @ w1^T + b1)
    gemm_kernel<true, false><<<gemm_ff1, 256>>>(h, w1, b1, nullptr, ff, NTOK, DFF, DM);
    // 9. out = x2 + ff @ w2^T + b2
    gemm_kernel<false, true><<<gemm_qkv, 256>>>(ff, w2, b2, x2, out, NTOK, DM, DFF);
}

// round 3
// speedup vs baseline: 1.3236x; 1.3236x over previous
#include <cuda_runtime.h>
#include <cstdint>
#include <math.h>

#define S_LEN 4096
#define BATCH 2
#define DM    768
#define DFF   3072
#define NH    12
#define DK    64
#define NTOK  (BATCH * S_LEN)

// ---------------- scratch (device globals: no allocation allowed) ----------
__device__ float g_h  [NTOK * DM];
__device__ float g_q  [NTOK * DM];
__device__ float g_k  [NTOK * DM];
__device__ float g_v  [NTOK * DM];
__device__ float g_ctx[NTOK * DM];
__device__ float g_x2 [NTOK * DM];
__device__ float g_ff [NTOK * DFF];

// ---------------- helpers --------------------------------------------------
__device__ __forceinline__ uint32_t f2tf32(float f) {
    uint32_t r; asm("cvt.rna.tf32.f32 %0, %1;" : "=r"(r) : "f"(f)); return r;
}

__device__ __forceinline__ void mma_tf32(float c[4], const uint4& a, const uint2& b) {
    asm volatile(
        "mma.sync.aligned.m16n8k8.row.col.f32.tf32.tf32.f32 "
        "{%0,%1,%2,%3}, {%4,%5,%6,%7}, {%8,%9}, {%0,%1,%2,%3};"
        : "+f"(c[0]), "+f"(c[1]), "+f"(c[2]), "+f"(c[3])
        : "r"(a.x), "r"(a.y), "r"(a.z), "r"(a.w), "r"(b.x), "r"(b.y));
}

// ---------------- layernorm-ish (scalar alpha/beta, ddof=1 std) -----------
__global__ void norm_kernel(const float* __restrict__ x, float* __restrict__ out,
                            const float* __restrict__ alpha, const float* __restrict__ beta) {
    const int row = blockIdx.x;
    const float* xr = x + (size_t)row * DM;
    float* orow = out + (size_t)row * DM;

    float v0 = xr[threadIdx.x];
    float v1 = xr[threadIdx.x + 256];
    float v2 = xr[threadIdx.x + 512];
    float s  = v0 + v1 + v2;
    float sq = v0 * v0 + v1 * v1 + v2 * v2;

    __shared__ float red0[8], red1[8];
    __shared__ float s_mean, s_scale, s_beta;
    #pragma unroll
    for (int o = 16; o > 0; o >>= 1) {
        s  += __shfl_xor_sync(0xffffffffu, s,  o);
        sq += __shfl_xor_sync(0xffffffffu, sq, o);
    }
    const int warp = threadIdx.x >> 5, lane = threadIdx.x & 31;
    if (lane == 0) { red0[warp] = s; red1[warp] = sq; }
    __syncthreads();
    if (threadIdx.x == 0) {
        float S = 0.f, SQ = 0.f;
        #pragma unroll
        for (int i = 0; i < 8; i++) { S += red0[i]; SQ += red1[i]; }
        const float mean = S / (float)DM;
        float var = (SQ - (float)DM * mean * mean) / (float)(DM - 1);
        var = fmaxf(var, 0.f);
        s_mean  = mean;
        s_scale = alpha[0] / (sqrtf(var) + 1e-6f);
        s_beta  = beta[0];
    }
    __syncthreads();
    const float mean = s_mean, scale = s_scale, bb = s_beta;
    orow[threadIdx.x]       = (v0 - mean) * scale + bb;
    orow[threadIdx.x + 256] = (v1 - mean) * scale + bb;
    orow[threadIdx.x + 512] = (v2 - mean) * scale + bb;
}

// =================== tf32 mma.sync GEMM ====================================
// C[M,N] = A[M,K] @ W[N,K]^T (+bias) (+res) (+relu)
// CTA tile 128x128, K-tile 32. 8 warps, each 64(m) x 32(n).
// smem holds tf32 tiles PRE-PERMUTED into m16n8k8 fragment layout:
//   A: [(k8, mt) tile][lane][4 regs]  -> LDS.128 per A-fragment
//   B: [(k8, nt) tile][lane][2 regs]  -> LDS.64  per B-fragment
template <bool RELU, bool HAS_RES>
__global__ void __launch_bounds__(256)
gemm_mma(const float* __restrict__ A, const float* __restrict__ W,
         const float* __restrict__ bias, const float* __restrict__ res,
         float* __restrict__ C, int M, int N, int K) {
    __shared__ uint32_t As[4096];   // 16KB: ((k8*8 + mt)*32 + lane)*4 + reg
    __shared__ uint32_t Bs[4096];   // 16KB: ((k8*16 + nt)*32 + lane)*2 + reg

    const int t    = threadIdx.x;
    const int lane = t & 31;
    const int wid  = t >> 5;
    const int wy   = wid >> 2;          // 0..1  (m half)
    const int wx   = wid & 3;           // 0..3  (n quarter)
    const int bm   = blockIdx.y * 128;
    const int bn   = blockIdx.x * 128;

    const float* Ab = A + (size_t)bm * K;
    const float* Wb = W + (size_t)bn * K;

    // per-thread staging coordinates: 4 float4 per matrix
    int rowp[4], gp[4];
    #pragma unroll
    for (int p = 0; p < 4; p++) {
        const int f = t + p * 256;
        rowp[p] = f >> 3;
        gp[p]   = f & 7;
    }

    float acc[4][4][4];
    #pragma unroll
    for (int i = 0; i < 4; i++)
        #pragma unroll
        for (int j = 0; j < 4; j++)
            #pragma unroll
            for (int r = 0; r < 4; r++) acc[i][j][r] = 0.f;

    float4 pa[4], pb[4];

    auto gload = [&](int k0) {
        #pragma unroll
        for (int p = 0; p < 4; p++) {
            pa[p] = *(const float4*)(Ab + (size_t)rowp[p] * K + k0 + gp[p] * 4);
            pb[p] = *(const float4*)(Wb + (size_t)rowp[p] * K + k0 + gp[p] * 4);
        }
    };

    auto sts = [&]() {
        #pragma unroll
        for (int p = 0; p < 4; p++) {
            const int row = rowp[p], g = gp[p];
            const int k8 = g >> 1, khi = g & 1;
            // A
            {
                const int mt = row >> 4, rr = row & 15;
                const int reg = (rr >> 3) + 2 * khi;
                const int base = ((k8 * 8 + mt) * 32 + (rr & 7) * 4) * 4 + reg;
                As[base +  0] = f2tf32(pa[p].x);
                As[base +  4] = f2tf32(pa[p].y);
                As[base +  8] = f2tf32(pa[p].z);
                As[base + 12] = f2tf32(pa[p].w);
            }
            // B
            {
                const int nt = row >> 3, nr = row & 7;
                const int base = ((k8 * 16 + nt) * 32 + nr * 4) * 2 + khi;
                Bs[base + 0] = f2tf32(pb[p].x);
                Bs[base + 2] = f2tf32(pb[p].y);
                Bs[base + 4] = f2tf32(pb[p].z);
                Bs[base + 6] = f2tf32(pb[p].w);
            }
        }
    };

    auto compute = [&]() {
        #pragma unroll
        for (int k8 = 0; k8 < 4; k8++) {
            uint4 af[4];
            uint2 bf[4];
            #pragma unroll
            for (int mt = 0; mt < 4; mt++)
                af[mt] = *(const uint4*)&As[((k8 * 8 + wy * 4 + mt) * 32 + lane) * 4];
            #pragma unroll
            for (int nt = 0; nt < 4; nt++)
                bf[nt] = *(const uint2*)&Bs[((k8 * 16 + wx * 4 + nt) * 32 + lane) * 2];
            #pragma unroll
            for (int mt = 0; mt < 4; mt++)
                #pragma unroll
                for (int nt = 0; nt < 4; nt++)
                    mma_tf32(acc[mt][nt], af[mt], bf[nt]);
        }
    };

    const int niter = K / 32;

    gload(0);
    sts();
    __syncthreads();

    for (int i = 0; i < niter; i++) {
        if (i + 1 < niter) gload((i + 1) * 32);
        compute();
        if (i + 1 < niter) {
            __syncthreads();   // all warps done reading current tile
            sts();
            __syncthreads();   // new tile visible
        }
    }

    // ---- epilogue: write accumulators directly (float2 per mma row) ----
    const int rbase = bm + wy * 64 + (lane >> 2);
    const int cbase = bn + wx * 32 + (lane & 3) * 2;
    #pragma unroll
    for (int mt = 0; mt < 4; mt++) {
        #pragma unroll
        for (int nt = 0; nt < 4; nt++) {
            const int c = cbase + nt * 8;
            const float b0 = bias[c], b1 = bias[c + 1];
            const int r0 = rbase + mt * 16;
            const int r1 = r0 + 8;
            float v0 = acc[mt][nt][0] + b0;
            float v1 = acc[mt][nt][1] + b1;
            float v2 = acc[mt][nt][2] + b0;
            float v3 = acc[mt][nt][3] + b1;
            if (HAS_RES) {
                const float2 q0 = *(const float2*)&res[(size_t)r0 * N + c];
                const float2 q1 = *(const float2*)&res[(size_t)r1 * N + c];
                v0 += q0.x; v1 += q0.y; v2 += q1.x; v3 += q1.y;
            }
            if (RELU) {
                v0 = fmaxf(v0, 0.f); v1 = fmaxf(v1, 0.f);
                v2 = fmaxf(v2, 0.f); v3 = fmaxf(v3, 0.f);
            }
            *(float2*)&C[(size_t)r0 * N + c] = make_float2(v0, v1);
            *(float2*)&C[(size_t)r1 * N + c] = make_float2(v2, v3);
        }
    }
}

// ---------------- flash attention, fp32, BM=BN=64, D=64 --------------------
#define ATT_STRIDE 65
#define ATT_SMEM_FLOATS (3 * 64 * ATT_STRIDE)

__global__ void __launch_bounds__(256, 2)
attn_kernel(const float* __restrict__ Q, const float* __restrict__ K,
            const float* __restrict__ V, const int* __restrict__ mask,
            float* __restrict__ O) {
    extern __shared__ float smem[];
    float* Qs  = smem;
    float* KVs = smem + 64 * ATT_STRIDE;
    float* Ss  = smem + 2 * 64 * ATT_STRIDE;
    __shared__ float mrow[64], lrow[64], frow[64];
    __shared__ int   mk[64];

    const int q0 = blockIdx.x * 64;
    const int h  = blockIdx.y;
    const int b  = blockIdx.z;
    const int t  = threadIdx.x;
    const int tx = t & 15, ty = t >> 4;

    const size_t base = (size_t)b * S_LEN * DM + (size_t)h * DK;

    for (int f = t; f < 64 * 16; f += 256) {
        const int row = f >> 4;
        const int dg  = (f & 15) * 4;
        float4 v4 = *(const float4*)(Q + base + (size_t)(q0 + row) * DM + dg);
        float* dst = Qs + row * ATT_STRIDE + dg;
        dst[0] = v4.x; dst[1] = v4.y; dst[2] = v4.z; dst[3] = v4.w;
    }
    if (t < 64) { mrow[t] = -INFINITY; lrow[t] = 0.f; }

    float o[4][4];
    #pragma unroll
    for (int i = 0; i < 4; i++)
        #pragma unroll
        for (int j = 0; j < 4; j++) o[i][j] = 0.f;

    __syncthreads();

    for (int k0 = 0; k0 < S_LEN; k0 += 64) {
        for (int f = t; f < 64 * 16; f += 256) {
            const int row = f >> 4;
            const int dg  = (f & 15) * 4;
            float4 v4 = *(const float4*)(K + base + (size_t)(k0 + row) * DM + dg);
            float* dst = KVs + row * ATT_STRIDE + dg;
            dst[0] = v4.x; dst[1] = v4.y; dst[2] = v4.z; dst[3] = v4.w;
        }
        if (t < 64) mk[t] = mask[(size_t)b * S_LEN + k0 + t];
        __syncthreads();

        float s[4][4];
        #pragma unroll
        for (int i = 0; i < 4; i++)
            #pragma unroll
            for (int j = 0; j < 4; j++) s[i][j] = 0.f;
        #pragma unroll 8
        for (int d = 0; d < 64; d++) {
            float a[4], bb[4];
            #pragma unroll
            for (int i = 0; i < 4; i++) a[i]  = Qs[(ty * 4 + i) * ATT_STRIDE + d];
            #pragma unroll
            for (int j = 0; j < 4; j++) bb[j] = KVs[(tx * 4 + j) * ATT_STRIDE + d];
            #pragma unroll
            for (int i = 0; i < 4; i++)
                #pragma unroll
                for (int j = 0; j < 4; j++) s[i][j] = fmaf(a[i], bb[j], s[i][j]);
        }
        #pragma unroll
        for (int i = 0; i < 4; i++)
            #pragma unroll
            for (int j = 0; j < 4; j++) {
                const int kj = tx * 4 + j;
                const float v = mk[kj] ? s[i][j] * 0.125f : -1e9f;
                Ss[(ty * 4 + i) * ATT_STRIDE + kj] = v;
            }
        __syncthreads();

        for (int f = t; f < 64 * 16; f += 256) {
            const int row = f >> 4;
            const int dg  = (f & 15) * 4;
            float4 v4 = *(const float4*)(V + base + (size_t)(k0 + row) * DM + dg);
            float* dst = KVs + row * ATT_STRIDE + dg;
            dst[0] = v4.x; dst[1] = v4.y; dst[2] = v4.z; dst[3] = v4.w;
        }

        {
            const int r = t >> 2, cc = t & 3;
            float mloc = -INFINITY;
            #pragma unroll
            for (int j = cc * 16; j < cc * 16 + 16; j++)
                mloc = fmaxf(mloc, Ss[r * ATT_STRIDE + j]);
            mloc = fmaxf(mloc, __shfl_xor_sync(0xffffffffu, mloc, 1));
            mloc = fmaxf(mloc, __shfl_xor_sync(0xffffffffu, mloc, 2));
            const float mold = mrow[r];
            const float mnew = fmaxf(mold, mloc);
            float lloc = 0.f;
            #pragma unroll
            for (int j = cc * 16; j < cc * 16 + 16; j++) {
                const float p = __expf(Ss[r * ATT_STRIDE + j] - mnew);
                Ss[r * ATT_STRIDE + j] = p;
                lloc += p;
            }
            lloc += __shfl_xor_sync(0xffffffffu, lloc, 1);
            lloc += __shfl_xor_sync(0xffffffffu, lloc, 2);
            if (cc == 0) {
                const float fac = __expf(mold - mnew);
                frow[r] = fac;
                lrow[r] = lrow[r] * fac + lloc;
                mrow[r] = mnew;
            }
        }
        __syncthreads();

        #pragma unroll
        for (int i = 0; i < 4; i++) {
            const float fac = frow[ty * 4 + i];
            #pragma unroll
            for (int j = 0; j < 4; j++) o[i][j] *= fac;
        }
        #pragma unroll 8
        for (int k = 0; k < 64; k++) {
            float a[4], bb[4];
            #pragma unroll
            for (int i = 0; i < 4; i++) a[i]  = Ss[(ty * 4 + i) * ATT_STRIDE + k];
            #pragma unroll
            for (int j = 0; j < 4; j++) bb[j] = KVs[k * ATT_STRIDE + tx * 4 + j];
            #pragma unroll
            for (int i = 0; i < 4; i++)
                #pragma unroll
                for (int j = 0; j < 4; j++) o[i][j] = fmaf(a[i], bb[j], o[i][j]);
        }
        __syncthreads();
    }

    #pragma unroll
    for (int i = 0; i < 4; i++) {
        const float inv = 1.f / lrow[ty * 4 + i];
        #pragma unroll
        for (int j = 0; j < 4; j++)
            O[base + (size_t)(q0 + ty * 4 + i) * DM + tx * 4 + j] = o[i][j] * inv;
    }
}

// ---------------------------------------------------------------------------
extern "C" void kernel_launch(void* const* d_in, const int* in_sizes, int n_in,
                              void* d_out, int out_size) {
    const float* x      = (const float*)d_in[0];
    const int*   mask   = (const int*)  d_in[1];
    const float* wq     = (const float*)d_in[2];
    const float* bq     = (const float*)d_in[3];
    const float* wk     = (const float*)d_in[4];
    const float* bk     = (const float*)d_in[5];
    const float* wv     = (const float*)d_in[6];
    const float* bv     = (const float*)d_in[7];
    const float* wo     = (const float*)d_in[8];
    const float* bo     = (const float*)d_in[9];
    const float* w1     = (const float*)d_in[10];
    const float* b1     = (const float*)d_in[11];
    const float* w2     = (const float*)d_in[12];
    const float* b2     = (const float*)d_in[13];
    const float* alpha1 = (const float*)d_in[14];
    const float* beta1  = (const float*)d_in[15];
    const float* alpha2 = (const float*)d_in[16];
    const float* beta2  = (const float*)d_in[17];
    float* out = (float*)d_out;

    float *h, *q, *k, *v, *ctx, *x2, *ff;
    cudaGetSymbolAddress((void**)&h,   g_h);
    cudaGetSymbolAddress((void**)&q,   g_q);
    cudaGetSymbolAddress((void**)&k,   g_k);
    cudaGetSymbolAddress((void**)&v,   g_v);
    cudaGetSymbolAddress((void**)&ctx, g_ctx);
    cudaGetSymbolAddress((void**)&x2,  g_x2);
    cudaGetSymbolAddress((void**)&ff,  g_ff);

    cudaFuncSetAttribute(attn_kernel, cudaFuncAttributeMaxDynamicSharedMemorySize,
                         ATT_SMEM_FLOATS * (int)sizeof(float));

    const dim3 g_qkv(DM / 128,  NTOK / 128);   // (6, 64)
    const dim3 g_ff1(DFF / 128, NTOK / 128);   // (24, 64)
    const dim3 attn_grid(S_LEN / 64, NH, BATCH);

    // 1. h = norm1(x)
    norm_kernel<<<NTOK, 256>>>(x, h, alpha1, beta1);
    // 2-4. q,k,v projections (tf32 mma.sync)
    gemm_mma<false, false><<<g_qkv, 256>>>(h, wq, bq, nullptr, q, NTOK, DM, DM);
    gemm_mma<false, false><<<g_qkv, 256>>>(h, wk, bk, nullptr, k, NTOK, DM, DM);
    gemm_mma<false, false><<<g_qkv, 256>>>(h, wv, bv, nullptr, v, NTOK, DM, DM);
    // 5. attention -> ctx
    attn_kernel<<<attn_grid, 256, ATT_SMEM_FLOATS * sizeof(float)>>>(q, k, v, mask, ctx);
    // 6. x2 = x + ctx @ wo^T + bo
    gemm_mma<false, true><<<g_qkv, 256>>>(ctx, wo, bo, x, x2, NTOK, DM, DM);
    // 7. h = norm2(x2)
    norm_kernel<<<NTOK, 256>>>(x2, h, alpha2, beta2);
    // 8. ff = relu(h @ w1^T + b1)
    gemm_mma<true, false><<<g_ff1, 256>>>(h, w1, b1, nullptr, ff, NTOK, DFF, DM);
    // 9. out = x2 + ff @ w2^T + b2
    gemm_mma<false, true><<<g_qkv, 256>>>(ff, w2, b2, x2, out, NTOK, DM, DFF);
}

// round 4
// speedup vs baseline: 1.9161x; 1.4476x over previous
#include <cuda_runtime.h>
#include <cstdint>
#include <math.h>

#define S_LEN 4096
#define BATCH 2
#define DM    768
#define DFF   3072
#define NH    12
#define DK    64
#define NTOK  (BATCH * S_LEN)

// ---------------- scratch (device globals: no allocation allowed) ----------
__device__ float g_h  [NTOK * DM];
__device__ float g_q  [NTOK * DM];
__device__ float g_k  [NTOK * DM];
__device__ float g_v  [NTOK * DM];
__device__ float g_ctx[NTOK * DM];
__device__ float g_x2 [NTOK * DM];
__device__ float g_ff [NTOK * DFF];

// ---------------- helpers --------------------------------------------------
__device__ __forceinline__ uint32_t f2tf32(float f) {
    uint32_t r; asm("cvt.rna.tf32.f32 %0, %1;" : "=r"(r) : "f"(f)); return r;
}

__device__ __forceinline__ void mma_tf32(float c[4], const uint4& a, const uint2& b) {
    asm volatile(
        "mma.sync.aligned.m16n8k8.row.col.f32.tf32.tf32.f32 "
        "{%0,%1,%2,%3}, {%4,%5,%6,%7}, {%8,%9}, {%0,%1,%2,%3};"
        : "+f"(c[0]), "+f"(c[1]), "+f"(c[2]), "+f"(c[3])
        : "r"(a.x), "r"(a.y), "r"(a.z), "r"(a.w), "r"(b.x), "r"(b.y));
}

// ---------------- layernorm-ish (scalar alpha/beta, ddof=1 std) -----------
__global__ void norm_kernel(const float* __restrict__ x, float* __restrict__ out,
                            const float* __restrict__ alpha, const float* __restrict__ beta) {
    const int row = blockIdx.x;
    const float* xr = x + (size_t)row * DM;
    float* orow = out + (size_t)row * DM;

    float v0 = xr[threadIdx.x];
    float v1 = xr[threadIdx.x + 256];
    float v2 = xr[threadIdx.x + 512];
    float s  = v0 + v1 + v2;
    float sq = v0 * v0 + v1 * v1 + v2 * v2;

    __shared__ float red0[8], red1[8];
    __shared__ float s_mean, s_scale, s_beta;
    #pragma unroll
    for (int o = 16; o > 0; o >>= 1) {
        s  += __shfl_xor_sync(0xffffffffu, s,  o);
        sq += __shfl_xor_sync(0xffffffffu, sq, o);
    }
    const int warp = threadIdx.x >> 5, lane = threadIdx.x & 31;
    if (lane == 0) { red0[warp] = s; red1[warp] = sq; }
    __syncthreads();
    if (threadIdx.x == 0) {
        float S = 0.f, SQ = 0.f;
        #pragma unroll
        for (int i = 0; i < 8; i++) { S += red0[i]; SQ += red1[i]; }
        const float mean = S / (float)DM;
        float var = (SQ - (float)DM * mean * mean) / (float)(DM - 1);
        var = fmaxf(var, 0.f);
        s_mean  = mean;
        s_scale = alpha[0] / (sqrtf(var) + 1e-6f);
        s_beta  = beta[0];
    }
    __syncthreads();
    const float mean = s_mean, scale = s_scale, bb = s_beta;
    orow[threadIdx.x]       = (v0 - mean) * scale + bb;
    orow[threadIdx.x + 256] = (v1 - mean) * scale + bb;
    orow[threadIdx.x + 512] = (v2 - mean) * scale + bb;
}

// =================== tf32 mma.sync GEMM (as round 3, proven) ===============
template <bool RELU, bool HAS_RES>
__global__ void __launch_bounds__(256)
gemm_mma(const float* __restrict__ A, const float* __restrict__ W,
         const float* __restrict__ bias, const float* __restrict__ res,
         float* __restrict__ C, int M, int N, int K) {
    __shared__ uint32_t As[4096];
    __shared__ uint32_t Bs[4096];

    const int t    = threadIdx.x;
    const int lane = t & 31;
    const int wid  = t >> 5;
    const int wy   = wid >> 2;
    const int wx   = wid & 3;
    const int bm   = blockIdx.y * 128;
    const int bn   = blockIdx.x * 128;

    const float* Ab = A + (size_t)bm * K;
    const float* Wb = W + (size_t)bn * K;

    int rowp[4], gp[4];
    #pragma unroll
    for (int p = 0; p < 4; p++) {
        const int f = t + p * 256;
        rowp[p] = f >> 3;
        gp[p]   = f & 7;
    }

    float acc[4][4][4];
    #pragma unroll
    for (int i = 0; i < 4; i++)
        #pragma unroll
        for (int j = 0; j < 4; j++)
            #pragma unroll
            for (int r = 0; r < 4; r++) acc[i][j][r] = 0.f;

    float4 pa[4], pb[4];

    auto gload = [&](int k0) {
        #pragma unroll
        for (int p = 0; p < 4; p++) {
            pa[p] = *(const float4*)(Ab + (size_t)rowp[p] * K + k0 + gp[p] * 4);
            pb[p] = *(const float4*)(Wb + (size_t)rowp[p] * K + k0 + gp[p] * 4);
        }
    };

    auto sts = [&]() {
        #pragma unroll
        for (int p = 0; p < 4; p++) {
            const int row = rowp[p], g = gp[p];
            const int k8 = g >> 1, khi = g & 1;
            {
                const int mt = row >> 4, rr = row & 15;
                const int reg = (rr >> 3) + 2 * khi;
                const int base = ((k8 * 8 + mt) * 32 + (rr & 7) * 4) * 4 + reg;
                As[base +  0] = f2tf32(pa[p].x);
                As[base +  4] = f2tf32(pa[p].y);
                As[base +  8] = f2tf32(pa[p].z);
                As[base + 12] = f2tf32(pa[p].w);
            }
            {
                const int nt = row >> 3, nr = row & 7;
                const int base = ((k8 * 16 + nt) * 32 + nr * 4) * 2 + khi;
                Bs[base + 0] = f2tf32(pb[p].x);
                Bs[base + 2] = f2tf32(pb[p].y);
                Bs[base + 4] = f2tf32(pb[p].z);
                Bs[base + 6] = f2tf32(pb[p].w);
            }
        }
    };

    auto compute = [&]() {
        #pragma unroll
        for (int k8 = 0; k8 < 4; k8++) {
            uint4 af[4];
            uint2 bf[4];
            #pragma unroll
            for (int mt = 0; mt < 4; mt++)
                af[mt] = *(const uint4*)&As[((k8 * 8 + wy * 4 + mt) * 32 + lane) * 4];
            #pragma unroll
            for (int nt = 0; nt < 4; nt++)
                bf[nt] = *(const uint2*)&Bs[((k8 * 16 + wx * 4 + nt) * 32 + lane) * 2];
            #pragma unroll
            for (int mt = 0; mt < 4; mt++)
                #pragma unroll
                for (int nt = 0; nt < 4; nt++)
                    mma_tf32(acc[mt][nt], af[mt], bf[nt]);
        }
    };

    const int niter = K / 32;

    gload(0);
    sts();
    __syncthreads();

    for (int i = 0; i < niter; i++) {
        if (i + 1 < niter) gload((i + 1) * 32);
        compute();
        if (i + 1 < niter) {
            __syncthreads();
            sts();
            __syncthreads();
        }
    }

    const int rbase = bm + wy * 64 + (lane >> 2);
    const int cbase = bn + wx * 32 + (lane & 3) * 2;
    #pragma unroll
    for (int mt = 0; mt < 4; mt++) {
        #pragma unroll
        for (int nt = 0; nt < 4; nt++) {
            const int c = cbase + nt * 8;
            const float b0 = bias[c], b1 = bias[c + 1];
            const int r0 = rbase + mt * 16;
            const int r1 = r0 + 8;
            float v0 = acc[mt][nt][0] + b0;
            float v1 = acc[mt][nt][1] + b1;
            float v2 = acc[mt][nt][2] + b0;
            float v3 = acc[mt][nt][3] + b1;
            if (HAS_RES) {
                const float2 q0 = *(const float2*)&res[(size_t)r0 * N + c];
                const float2 q1 = *(const float2*)&res[(size_t)r1 * N + c];
                v0 += q0.x; v1 += q0.y; v2 += q1.x; v3 += q1.y;
            }
            if (RELU) {
                v0 = fmaxf(v0, 0.f); v1 = fmaxf(v1, 0.f);
                v2 = fmaxf(v2, 0.f); v3 = fmaxf(v3, 0.f);
            }
            *(float2*)&C[(size_t)r0 * N + c] = make_float2(v0, v1);
            *(float2*)&C[(size_t)r1 * N + c] = make_float2(v2, v3);
        }
    }
}

// =================== tf32 mma.sync flash attention =========================
// CTA: 64 queries (one (b,h) pair), BN=64 keys/iter, D=64.
// 8 warps: wy=wid&3 (m16 tile), wx=wid>>2 (n32 half).
// smem: Qs (A-layout), Ks (B-layout n=key,k=d), Vs (B-layout n=d,k=key),
//       Ps (A-layout m=query,k=key), red[128], mk[64].
#define ATT_SMEM (4 * 16384 + 128 * 4 + 64 * 4)

__global__ void __launch_bounds__(256)
attn_mma(const float* __restrict__ Q, const float* __restrict__ K,
         const float* __restrict__ V, const int* __restrict__ mask,
         float* __restrict__ O) {
    extern __shared__ char smraw[];
    uint32_t* Qs = (uint32_t*)smraw;
    uint32_t* Ks = Qs + 4096;
    uint32_t* Vs = Ks + 4096;
    uint32_t* Ps = Vs + 4096;
    float*    red = (float*)(Ps + 4096);   // [2][64]
    int*      mk  = (int*)(red + 128);     // [64]

    const int t = threadIdx.x, lane = t & 31, wid = t >> 5;
    const int wy = wid & 3, wx = wid >> 2;
    const int q0 = blockIdx.x * 64;
    const int h  = blockIdx.y, b = blockIdx.z;
    const size_t base = (size_t)b * S_LEN * DM + (size_t)h * DK;

    // ---- stage Q once into A-fragment layout ----
    #pragma unroll
    for (int p = 0; p < 4; p++) {
        const int f = t + p * 256;          // 1024 float4
        const int row = f >> 4, g = f & 15; // 16 float4 per 64-wide row
        float4 v4 = *(const float4*)(Q + base + (size_t)(q0 + row) * DM + g * 4);
        const int mt = row >> 4, rr = row & 15;
        const int k8 = g >> 1, khi = g & 1;
        const int reg = (rr >> 3) + 2 * khi;
        const int bidx = ((k8 * 4 + mt) * 32 + (rr & 7) * 4) * 4 + reg;
        Qs[bidx +  0] = f2tf32(v4.x);
        Qs[bidx +  4] = f2tf32(v4.y);
        Qs[bidx +  8] = f2tf32(v4.z);
        Qs[bidx + 12] = f2tf32(v4.w);
    }

    const int rloc0 = wy * 16 + (lane >> 2);   // CTA-local row of c0/c1
    const int rloc1 = rloc0 + 8;               // c2/c3

    float m0 = -INFINITY, m1 = -INFINITY, l0 = 0.f, l1 = 0.f;
    float o[4][4];
    #pragma unroll
    for (int i = 0; i < 4; i++)
        #pragma unroll
        for (int j = 0; j < 4; j++) o[i][j] = 0.f;

    for (int k0 = 0; k0 < S_LEN; k0 += 64) {
        // ---- stage K (B-layout: n=key, k=d) and V (B-layout: n=d, k=key) ----
        #pragma unroll
        for (int p = 0; p < 4; p++) {
            const int f = t + p * 256;
            const int row = f >> 4, g = f & 15;
            float4 kv = *(const float4*)(K + base + (size_t)(k0 + row) * DM + g * 4);
            {
                const int nt = row >> 3, nr = row & 7;
                const int k8 = g >> 1, khi = g & 1;
                const int bidx = ((k8 * 8 + nt) * 32 + nr * 4) * 2 + khi;
                Ks[bidx + 0] = f2tf32(kv.x);
                Ks[bidx + 2] = f2tf32(kv.y);
                Ks[bidx + 4] = f2tf32(kv.z);
                Ks[bidx + 6] = f2tf32(kv.w);
            }
            float4 vv = *(const float4*)(V + base + (size_t)(k0 + row) * DM + g * 4);
            {
                const int k8 = row >> 3, klo = row & 3, khi = (row >> 2) & 1;
                const float vj[4] = {vv.x, vv.y, vv.z, vv.w};
                #pragma unroll
                for (int j = 0; j < 4; j++) {
                    const int n = g * 4 + j;
                    const int nt = n >> 3, nr = n & 7;
                    Vs[((k8 * 8 + nt) * 32 + nr * 4 + klo) * 2 + khi] = f2tf32(vj[j]);
                }
            }
        }
        if (t < 64) mk[t] = mask[(size_t)b * S_LEN + k0 + t];
        __syncthreads();

        // ---- S = Q K^T ----
        float s[4][4];
        #pragma unroll
        for (int nt = 0; nt < 4; nt++)
            #pragma unroll
            for (int r = 0; r < 4; r++) s[nt][r] = 0.f;
        #pragma unroll
        for (int k8 = 0; k8 < 8; k8++) {
            const uint4 af = *(const uint4*)&Qs[((k8 * 4 + wy) * 32 + lane) * 4];
            #pragma unroll
            for (int nt = 0; nt < 4; nt++) {
                const uint2 bf = *(const uint2*)&Ks[((k8 * 8 + wx * 4 + nt) * 32 + lane) * 2];
                mma_tf32(s[nt], af, bf);
            }
        }

        // ---- mask + scale + row max ----
        float mx0 = -INFINITY, mx1 = -INFINITY;
        #pragma unroll
        for (int nt = 0; nt < 4; nt++) {
            const int c = wx * 32 + nt * 8 + (lane & 3) * 2;
            const bool ma = mk[c] != 0, mb = mk[c + 1] != 0;
            s[nt][0] = ma ? s[nt][0] * 0.125f : -1e9f;
            s[nt][1] = mb ? s[nt][1] * 0.125f : -1e9f;
            s[nt][2] = ma ? s[nt][2] * 0.125f : -1e9f;
            s[nt][3] = mb ? s[nt][3] * 0.125f : -1e9f;
            mx0 = fmaxf(mx0, fmaxf(s[nt][0], s[nt][1]));
            mx1 = fmaxf(mx1, fmaxf(s[nt][2], s[nt][3]));
        }
        mx0 = fmaxf(mx0, __shfl_xor_sync(0xffffffffu, mx0, 1));
        mx0 = fmaxf(mx0, __shfl_xor_sync(0xffffffffu, mx0, 2));
        mx1 = fmaxf(mx1, __shfl_xor_sync(0xffffffffu, mx1, 1));
        mx1 = fmaxf(mx1, __shfl_xor_sync(0xffffffffu, mx1, 2));
        if ((lane & 3) == 0) {
            red[wx * 64 + rloc0] = mx0;
            red[wx * 64 + rloc1] = mx1;
        }
        __syncthreads();
        const float mn0 = fmaxf(m0, fmaxf(red[rloc0], red[64 + rloc0]));
        const float mn1 = fmaxf(m1, fmaxf(red[rloc1], red[64 + rloc1]));
        const float fac0 = __expf(m0 - mn0);
        const float fac1 = __expf(m1 - mn1);
        m0 = mn0; m1 = mn1;

        // ---- exp, write P into A-layout, update l, rescale O ----
        float sum0 = 0.f, sum1 = 0.f;
        #pragma unroll
        for (int nt = 0; nt < 4; nt++) {
            const float p0 = __expf(s[nt][0] - mn0);
            const float p1 = __expf(s[nt][1] - mn0);
            const float p2 = __expf(s[nt][2] - mn1);
            const float p3 = __expf(s[nt][3] - mn1);
            sum0 += p0 + p1;
            sum1 += p2 + p3;
            const int kk  = wx * 32 + nt * 8 + (lane & 3) * 2;
            const int k8  = kk >> 3;
            const int kk7 = kk & 7;
            const int khi = kk7 >> 2, klo = kk7 & 3;
            const int idx = ((k8 * 4 + wy) * 32 + (lane >> 2) * 4 + klo) * 4 + 2 * khi;
            Ps[idx + 0] = f2tf32(p0);   // (rloc0, kk)
            Ps[idx + 4] = f2tf32(p1);   // (rloc0, kk+1)
            Ps[idx + 1] = f2tf32(p2);   // (rloc1, kk)
            Ps[idx + 5] = f2tf32(p3);   // (rloc1, kk+1)
            o[nt][0] *= fac0; o[nt][1] *= fac0;
            o[nt][2] *= fac1; o[nt][3] *= fac1;
        }
        l0 = l0 * fac0 + sum0;
        l1 = l1 * fac1 + sum1;
        __syncthreads();

        // ---- O += P V ----
        #pragma unroll
        for (int k8 = 0; k8 < 8; k8++) {
            const uint4 af = *(const uint4*)&Ps[((k8 * 4 + wy) * 32 + lane) * 4];
            #pragma unroll
            for (int nt = 0; nt < 4; nt++) {
                const uint2 bf = *(const uint2*)&Vs[((k8 * 8 + wx * 4 + nt) * 32 + lane) * 2];
                mma_tf32(o[nt], af, bf);
            }
        }
        __syncthreads();   // Ks/Vs/Ps/red free for next iteration
    }

    // ---- final l reduction + store ----
    l0 += __shfl_xor_sync(0xffffffffu, l0, 1);
    l0 += __shfl_xor_sync(0xffffffffu, l0, 2);
    l1 += __shfl_xor_sync(0xffffffffu, l1, 1);
    l1 += __shfl_xor_sync(0xffffffffu, l1, 2);
    if ((lane & 3) == 0) {
        red[wx * 64 + rloc0] = l0;
        red[wx * 64 + rloc1] = l1;
    }
    __syncthreads();
    const float inv0 = 1.f / (red[rloc0] + red[64 + rloc0]);
    const float inv1 = 1.f / (red[rloc1] + red[64 + rloc1]);

    const size_t row0 = q0 + rloc0;
    #pragma unroll
    for (int nt = 0; nt < 4; nt++) {
        const int c = wx * 32 + nt * 8 + (lane & 3) * 2;
        *(float2*)&O[base + row0 * DM + c] =
            make_float2(o[nt][0] * inv0, o[nt][1] * inv0);
        *(float2*)&O[base + (row0 + 8) * DM + c] =
            make_float2(o[nt][2] * inv1, o[nt][3] * inv1);
    }
}

// ---------------------------------------------------------------------------
extern "C" void kernel_launch(void* const* d_in, const int* in_sizes, int n_in,
                              void* d_out, int out_size) {
    const float* x      = (const float*)d_in[0];
    const int*   mask   = (const int*)  d_in[1];
    const float* wq     = (const float*)d_in[2];
    const float* bq     = (const float*)d_in[3];
    const float* wk     = (const float*)d_in[4];
    const float* bk     = (const float*)d_in[5];
    const float* wv     = (const float*)d_in[6];
    const float* bv     = (const float*)d_in[7];
    const float* wo     = (const float*)d_in[8];
    const float* bo     = (const float*)d_in[9];
    const float* w1     = (const float*)d_in[10];
    const float* b1     = (const float*)d_in[11];
    const float* w2     = (const float*)d_in[12];
    const float* b2     = (const float*)d_in[13];
    const float* alpha1 = (const float*)d_in[14];
    const float* beta1  = (const float*)d_in[15];
    const float* alpha2 = (const float*)d_in[16];
    const float* beta2  = (const float*)d_in[17];
    float* out = (float*)d_out;

    float *h, *q, *k, *v, *ctx, *x2, *ff;
    cudaGetSymbolAddress((void**)&h,   g_h);
    cudaGetSymbolAddress((void**)&q,   g_q);
    cudaGetSymbolAddress((void**)&k,   g_k);
    cudaGetSymbolAddress((void**)&v,   g_v);
    cudaGetSymbolAddress((void**)&ctx, g_ctx);
    cudaGetSymbolAddress((void**)&x2,  g_x2);
    cudaGetSymbolAddress((void**)&ff,  g_ff);

    cudaFuncSetAttribute(attn_mma, cudaFuncAttributeMaxDynamicSharedMemorySize, ATT_SMEM);

    const dim3 g_qkv(DM / 128,  NTOK / 128);   // (6, 64)
    const dim3 g_ff1(DFF / 128, NTOK / 128);   // (24, 64)
    const dim3 attn_grid(S_LEN / 64, NH, BATCH);

    // 1. h = norm1(x)
    norm_kernel<<<NTOK, 256>>>(x, h, alpha1, beta1);
    // 2-4. q,k,v projections (tf32 mma.sync)
    gemm_mma<false, false><<<g_qkv, 256>>>(h, wq, bq, nullptr, q, NTOK, DM, DM);
    gemm_mma<false, false><<<g_qkv, 256>>>(h, wk, bk, nullptr, k, NTOK, DM, DM);
    gemm_mma<false, false><<<g_qkv, 256>>>(h, wv, bv, nullptr, v, NTOK, DM, DM);
    // 5. attention -> ctx (tf32 mma.sync flash attention)
    attn_mma<<<attn_grid, 256, ATT_SMEM>>>(q, k, v, mask, ctx);
    // 6. x2 = x + ctx @ wo^T + bo
    gemm_mma<false, true><<<g_qkv, 256>>>(ctx, wo, bo, x, x2, NTOK, DM, DM);
    // 7. h = norm2(x2)
    norm_kernel<<<NTOK, 256>>>(x2, h, alpha2, beta2);
    // 8. ff = relu(h @ w1^T + b1)
    gemm_mma<true, false><<<g_ff1, 256>>>(h, w1, b1, nullptr, ff, NTOK, DFF, DM);
    // 9. out = x2 + ff @ w2^T + b2
    gemm_mma<false, true><<<g_qkv, 256>>>(ff, w2, b2, x2, out, NTOK, DM, DFF);
}